// round 2
// baseline (speedup 1.0000x reference)
#include <cuda_runtime.h>

// ReactantCentreIdentify — fused segment-mean-gate-concat.
//   node_rep      [N=400000, D=300] f32
//   batch         [N] i32, SORTED ascending in [0, B)
//   primary_label [N] i32 in {-1, 0}
//   num_graphs    B = 4096 (fixed problem shape)
//   out           [N, 600] f32 = [node_rep | cond_pool[batch]]
//
// Persistent CTAs (608 = 152 SMs x 4), each striding over graphs. batch sorted
// => graph g is contiguous rows [s, e) via two binary searches. Pass 1 streams
// rows with unroll-4 front-batched LDG.128 (MLP=4): copy left half, accumulate
// condition rows in registers (column ownership, no atomics). Reduce across
// y-lanes in shared, gate on last-node label, scale by 1/max(cnt,1). Pass 2
// broadcasts the pooled vector into the right half.

#define D4     75          // D/4 float4 per input row
#define OUT4   150         // 2D/4 float4 per output row
#define BY     4           // row lanes per block
#define NGRAPH 4096
#define GRID   608         // 152 SMs * 4 resident CTAs — one wave, no tail

__global__ __launch_bounds__(D4 * BY)
void reactant_centre_kernel(const float4* __restrict__ x4,     // [N, 75]
                            const int*    __restrict__ batch,  // [N]
                            const int*    __restrict__ label,  // [N]
                            float4*       __restrict__ out4,   // [N, 150]
                            int n)
{
    const int c4  = threadIdx.x;   // 0..74  (float4 column)
    const int ry  = threadIdx.y;   // 0..3   (row lane)
    const int tid = ry * D4 + c4;

    __shared__ int    s_se[2];
    __shared__ float4 s_acc[BY][D4];
    __shared__ int    s_cnt[BY];
    __shared__ float4 s_pool[D4];

    for (int g = blockIdx.x; g < NGRAPH; g += gridDim.x) {
        // lower_bound for g and g+1 -> contiguous row range [s, e)
        if (tid < 2) {
            int target = g + tid;
            int lo = 0, hi = n;
            while (lo < hi) {
                int mid = (lo + hi) >> 1;
                if (batch[mid] < target) lo = mid + 1; else hi = mid;
            }
            s_se[tid] = lo;
        }
        __syncthreads();
        const int s = s_se[0];
        const int e = s_se[1];

        // ---- Pass 1: copy left half + accumulate condition rows ----
        float4 acc = make_float4(0.f, 0.f, 0.f, 0.f);
        int cnt = 0;
        int r = s + ry;

        for (; r + 3 * BY < e; r += 4 * BY) {
            const int r0 = r, r1 = r + BY, r2 = r + 2 * BY, r3 = r + 3 * BY;
            // front-batch 4 independent 128-bit loads (MLP = 4)
            float4 v0 = __ldcs(x4 + (long)r0 * D4 + c4);
            float4 v1 = __ldcs(x4 + (long)r1 * D4 + c4);
            float4 v2 = __ldcs(x4 + (long)r2 * D4 + c4);
            float4 v3 = __ldcs(x4 + (long)r3 * D4 + c4);
            int l0 = label[r0], l1 = label[r1], l2 = label[r2], l3 = label[r3];

            __stcs(out4 + (long)r0 * OUT4 + c4, v0);
            __stcs(out4 + (long)r1 * OUT4 + c4, v1);
            __stcs(out4 + (long)r2 * OUT4 + c4, v2);
            __stcs(out4 + (long)r3 * OUT4 + c4, v3);

            if (l0 == -1) { acc.x += v0.x; acc.y += v0.y; acc.z += v0.z; acc.w += v0.w; cnt++; }
            if (l1 == -1) { acc.x += v1.x; acc.y += v1.y; acc.z += v1.z; acc.w += v1.w; cnt++; }
            if (l2 == -1) { acc.x += v2.x; acc.y += v2.y; acc.z += v2.z; acc.w += v2.w; cnt++; }
            if (l3 == -1) { acc.x += v3.x; acc.y += v3.y; acc.z += v3.z; acc.w += v3.w; cnt++; }
        }
        for (; r < e; r += BY) {
            float4 v = __ldcs(x4 + (long)r * D4 + c4);
            int   l = label[r];
            __stcs(out4 + (long)r * OUT4 + c4, v);
            if (l == -1) { acc.x += v.x; acc.y += v.y; acc.z += v.z; acc.w += v.w; cnt++; }
        }

        s_acc[ry][c4] = acc;
        if (c4 == 0) s_cnt[ry] = cnt;
        __syncthreads();

        // Gate: pool only if the LAST node of the graph is a condition node.
        const bool flag = (e > s) && (label[e - 1] == -1);

        if (ry == 0) {
            float4 a = s_acc[0][c4];
            float4 b = s_acc[1][c4];
            float4 c = s_acc[2][c4];
            float4 d = s_acc[3][c4];
            float tc  = (float)(s_cnt[0] + s_cnt[1] + s_cnt[2] + s_cnt[3]);
            float inv = flag ? (1.0f / fmaxf(tc, 1.0f)) : 0.0f;
            s_pool[c4] = make_float4((a.x + b.x + c.x + d.x) * inv,
                                     (a.y + b.y + c.y + d.y) * inv,
                                     (a.z + b.z + c.z + d.z) * inv,
                                     (a.w + b.w + c.w + d.w) * inv);
        }
        __syncthreads();

        // ---- Pass 2: broadcast pooled vector into right half ----
        const float4 p = s_pool[c4];
        int r2 = s + ry;
        for (; r2 + 3 * BY < e; r2 += 4 * BY) {
            __stcs(out4 + (long)(r2         ) * OUT4 + D4 + c4, p);
            __stcs(out4 + (long)(r2 +     BY) * OUT4 + D4 + c4, p);
            __stcs(out4 + (long)(r2 + 2 * BY) * OUT4 + D4 + c4, p);
            __stcs(out4 + (long)(r2 + 3 * BY) * OUT4 + D4 + c4, p);
        }
        for (; r2 < e; r2 += BY) {
            __stcs(out4 + (long)r2 * OUT4 + D4 + c4, p);
        }
    }
}

extern "C" void kernel_launch(void* const* d_in, const int* in_sizes, int n_in,
                              void* d_out, int out_size)
{
    const float* node_rep = (const float*)d_in[0];
    const int*   batch    = (const int*)d_in[1];
    const int*   label    = (const int*)d_in[2];
    (void)n_in; (void)out_size;

    const int n = in_sizes[1];        // N from batch array

    dim3 block(D4, BY);               // 75 x 4 = 300 threads
    reactant_centre_kernel<<<GRID, block>>>((const float4*)node_rep, batch, label,
                                            (float4*)d_out, n);
}

// round 3
// speedup vs baseline: 1.1292x; 1.1292x over previous
#include <cuda_runtime.h>

// ReactantCentreIdentify — fused segment-mean-gate-concat.
//   node_rep      [N=400000, D=300] f32
//   batch         [N] i32, SORTED ascending in [0, B)
//   primary_label [N] i32 in {-1, 0}
//   out           [N, 600] f32 = [node_rep | cond_pool[batch]]
//
// R1 structure (proven 71.4% DRAM, 87% occ): one CTA per graph, grid=4096,
// block (75,4)=300 thr, register accumulation with column ownership.
// R3 change: L2 prefetch of rows 2 iterations (8 rows) ahead, issued by one
// thread per 128B line — raises DRAM-level MLP without register cost, so
// occupancy stays at 6 CTAs/SM (enforced by launch_bounds).

#define D4   75          // D/4 float4 per input row
#define OUT4 150         // 2D/4 float4 per output row
#define BY   4           // row lanes per block
#define PF   2           // prefetch distance in loop iterations (PF*BY rows)

__global__ __launch_bounds__(D4 * BY, 6)
void reactant_centre_kernel(const float4* __restrict__ x4,     // [N, 75]
                            const int*    __restrict__ batch,  // [N]
                            const int*    __restrict__ label,  // [N]
                            float4*       __restrict__ out4,   // [N, 150]
                            int n)
{
    const int g   = blockIdx.x;
    const int c4  = threadIdx.x;   // 0..74  (float4 column)
    const int ry  = threadIdx.y;   // 0..3   (row lane)
    const int tid = ry * D4 + c4;

    __shared__ int    s_se[2];
    __shared__ float4 s_acc[BY][D4];
    __shared__ int    s_cnt[BY];
    __shared__ float4 s_pool[D4];

    // lower_bound for g and g+1 -> contiguous row range [s, e)
    if (tid < 2) {
        int target = g + tid;
        int lo = 0, hi = n;
        while (lo < hi) {
            int mid = (lo + hi) >> 1;
            if (batch[mid] < target) lo = mid + 1; else hi = mid;
        }
        s_se[tid] = lo;
    }
    __syncthreads();
    const int s = s_se[0];
    const int e = s_se[1];

    const bool do_pf = ((c4 & 7) == 0);   // one prefetcher per 128B line

    // ---- Pass 1: copy left half + accumulate condition rows ----
    float4 acc = make_float4(0.f, 0.f, 0.f, 0.f);
    int cnt = 0;
    for (int r = s + ry; r < e; r += BY) {
        // L2 prefetch PF iterations ahead (clamped; harmless overlap at tail)
        if (do_pf) {
            int rp = r + PF * BY;
            if (rp > e - 1) rp = e - 1;
            const float4* pp = x4 + (long)rp * D4 + c4;
            asm volatile("prefetch.global.L2 [%0];" :: "l"(pp));
        }
        float4 v = x4[(long)r * D4 + c4];
        int   l = label[r];
        out4[(long)r * OUT4 + c4] = v;
        if (l == -1) {
            acc.x += v.x; acc.y += v.y; acc.z += v.z; acc.w += v.w;
            cnt++;
        }
    }
    s_acc[ry][c4] = acc;
    if (c4 == 0) s_cnt[ry] = cnt;
    __syncthreads();

    // Gate: pool only if the LAST node of the graph is a condition node.
    const bool flag = (e > s) && (label[e - 1] == -1);

    if (ry == 0) {
        float4 a = s_acc[0][c4];
        float4 b = s_acc[1][c4];
        float4 c = s_acc[2][c4];
        float4 d = s_acc[3][c4];
        float tc  = (float)(s_cnt[0] + s_cnt[1] + s_cnt[2] + s_cnt[3]);
        float inv = flag ? (1.0f / fmaxf(tc, 1.0f)) : 0.0f;
        s_pool[c4] = make_float4((a.x + b.x + c.x + d.x) * inv,
                                 (a.y + b.y + c.y + d.y) * inv,
                                 (a.z + b.z + c.z + d.z) * inv,
                                 (a.w + b.w + c.w + d.w) * inv);
    }
    __syncthreads();

    // ---- Pass 2: broadcast pooled vector into right half ----
    const float4 p = s_pool[c4];
    for (int r = s + ry; r < e; r += BY) {
        out4[(long)r * OUT4 + D4 + c4] = p;
    }
}

extern "C" void kernel_launch(void* const* d_in, const int* in_sizes, int n_in,
                              void* d_out, int out_size)
{
    const float* node_rep = (const float*)d_in[0];
    const int*   batch    = (const int*)d_in[1];
    const int*   label    = (const int*)d_in[2];
    (void)n_in; (void)out_size;

    const int n = in_sizes[1];        // N from batch array
    const int B = 4096;               // num_graphs (fixed problem shape)

    dim3 block(D4, BY);               // 75 x 4 = 300 threads
    reactant_centre_kernel<<<B, block>>>((const float4*)node_rep, batch, label,
                                         (float4*)d_out, n);
}